// round 8
// baseline (speedup 1.0000x reference)
#include <cuda_runtime.h>
#include <cstdint>

#define NH       4096
#define NH4      1024
#define NSTAGE   252                // 63 RK4 steps * 4 stages
#define NOUT     128
#define CMB4     1152

#define GRID     147
#define NW       16
#define NTHREADS 512
#define RPB      28                 // rows per CTA
#define SW       14                 // rows base..base+13 in SMEM

// smem: [14 Wf rows = 229376][pbuf 16*33*4 = 2112][dt 256] = 231744 <= 232448
#define OFF_PBUF  229376
#define OFF_DT    231488
#define SMEM_BYTES 231744

__device__ __align__(16) float gV[2][4128];   // rows 0..4115 used
__device__ __align__(16) float gHn[4128];
__device__ unsigned g_arrive;                 // single monotonic barrier counter

__device__ __forceinline__ unsigned bar_arrive() {
    __syncthreads();
    unsigned target = 0;
    if (threadIdx.x == 0) {
        unsigned old;
        asm volatile("atom.add.release.gpu.u32 %0, [%1], 1;"
                     : "=r"(old) : "l"(&g_arrive) : "memory");
        target = old - old % GRID + GRID;
    }
    return target;
}

__device__ __forceinline__ void bar_wait(unsigned target) {
    if (threadIdx.x == 0) {
        unsigned cur;
        do {
            asm volatile("ld.acquire.gpu.u32 %0, [%1];"
                         : "=r"(cur) : "l"(&g_arrive) : "memory");
        } while ((int)(cur - target) < 0);
    }
    __syncthreads();
}

__device__ __forceinline__ float warp_sum(float v) {
    #pragma unroll
    for (int o = 16; o; o >>= 1) v += __shfl_xor_sync(0xffffffffu, v, o);
    return v;
}

#define FMA4(A, Q, B) \
    { (A).x = fmaf((Q).x, (B).x, (A).x); (A).y = fmaf((Q).y, (B).y, (A).y); \
      (A).z = fmaf((Q).z, (B).z, (A).z); (A).w = fmaf((Q).w, (B).w, (A).w); }

__global__ void __launch_bounds__(NTHREADS, 1)
ode_rnn_kernel(const float* __restrict__ x,
               const float* __restrict__ h0,
               const float* __restrict__ t,
               const float* __restrict__ Wf,
               const float* __restrict__ bf,
               const float* __restrict__ Wi,
               const float* __restrict__ bi,
               const float* __restrict__ Wo,
               const float* __restrict__ bo,
               float* __restrict__ out)
{
    extern __shared__ char smem[];
    float4* wsm4  = (float4*)smem;                    // 14 rows x 1024 f4
    float*  psm   = (float*)(smem + OFF_PBUF);        // [16][33]
    float*  dtbuf = (float*)(smem + OFF_DT);

    const int tid  = threadIdx.x;
    const int w    = tid >> 5;
    const int lane = tid & 31;
    const int base = blockIdx.x * RPB;

    const float4* Wf4 = (const float4*)Wf;
    const int kb = 64 * w + lane;                     // this lane's first f4 index

    // ---- SMEM preload: rows base..base+13 (clamped) ----
    for (int idx = tid; idx < SW * NH4; idx += NTHREADS) {
        int slot   = idx >> 10;
        int within = idx & 1023;
        int gr     = min(base + slot, NH - 1);
        wsm4[idx]  = __ldg(Wf4 + (size_t)gr * NH4 + within);
    }
    if (tid < NSTAGE / 4) dtbuf[tid] = __ldg(t + tid + 1) - __ldg(t + tid);

    // L2 weight rows: base+14 .. base+27 (clamp block so all 14 rows valid)
    const int b2 = min(base + SW, NH - SW);
    const float4* pW2 = Wf4 + (size_t)b2 * NH4 + kb;  // row r offset: r*NH4

    // RK4 row ownership (phase 2): warp w < 14 owns rows base+2w, base+2w+1
    const int rA  = base + 2 * w;
    const int cAi = min(rA,     NH - 1);
    const int cBi = min(rA + 1, NH - 1);

    float hhA = 0.f, hhB = 0.f, bfA = 0.f, bfB = 0.f;
    if (w < 14) {
        hhA = __ldg(h0 + cAi);  hhB = __ldg(h0 + cBi);
        bfA = __ldg(bf + cAi);  bfB = __ldg(bf + cBi);
        if (lane == 0) *(float2*)(&gV[0][rA]) = make_float2(hhA, hhB);
    }

    unsigned tgt = bar_arrive();
    bar_wait(tgt);

    int p = 0;
    float k1A = 0.f, k2A = 0.f, k3A = 0.f;
    float k1B = 0.f, k2B = 0.f, k3B = 0.f;

    #pragma unroll 1
    for (int sg = 0; sg < NSTAGE; ++sg) {
        const float dt = dtbuf[sg >> 2];
        const int   u  = sg & 3;

        // ---- v slice straight into registers (L2-coherent) ----
        const float4* vsrc = (const float4*)gV[p];
        const float4 v0 = __ldcg(vsrc + kb);
        const float4 v1 = __ldcg(vsrc + kb + 32);

        // ---- partial dots for all 28 rows over this warp's K-slice ----
        float part[28];
        #pragma unroll
        for (int r = 0; r < 28; ++r) part[r] = 0.f;

        #pragma unroll
        for (int r = 0; r < 14; ++r) {
            // L2 row (base+14+r) — issue loads early
            float4 b0 = __ldg(pW2 + (size_t)r * NH4);
            float4 b1 = __ldg(pW2 + (size_t)r * NH4 + 32);
            // SMEM row r
            float4 a0 = wsm4[r * NH4 + kb];
            float4 a1 = wsm4[r * NH4 + kb + 32];
            float pa = part[r], pb = part[14 + r];
            pa = fmaf(a0.x, v0.x, pa); pa = fmaf(a0.y, v0.y, pa);
            pa = fmaf(a0.z, v0.z, pa); pa = fmaf(a0.w, v0.w, pa);
            pa = fmaf(a1.x, v1.x, pa); pa = fmaf(a1.y, v1.y, pa);
            pa = fmaf(a1.z, v1.z, pa); pa = fmaf(a1.w, v1.w, pa);
            pb = fmaf(b0.x, v0.x, pb); pb = fmaf(b0.y, v0.y, pb);
            pb = fmaf(b0.z, v0.z, pb); pb = fmaf(b0.w, v0.w, pb);
            pb = fmaf(b1.x, v1.x, pb); pb = fmaf(b1.y, v1.y, pb);
            pb = fmaf(b1.z, v1.z, pb); pb = fmaf(b1.w, v1.w, pb);
            part[r] = pa; part[14 + r] = pb;
        }

        // ---- split-butterfly reduce: 28 values -> low half rows 0..13, high rows 14..27 ----
        float red[14];
        #pragma unroll
        for (int j = 0; j < 14; ++j) {
            float lo = part[j]      + __shfl_xor_sync(0xffffffffu, part[j],      16);
            float hi = part[14 + j] + __shfl_xor_sync(0xffffffffu, part[14 + j], 16);
            red[j] = (lane < 16) ? lo : hi;
        }
        #pragma unroll
        for (int m = 8; m >= 1; m >>= 1) {
            #pragma unroll
            for (int j = 0; j < 14; ++j)
                red[j] += __shfl_xor_sync(0xffffffffu, red[j], m);
        }
        // lane 0 holds rows 0..13 totals; lane 16 holds rows 14..27 totals
        if (lane == 0) {
            #pragma unroll
            for (int j = 0; j < 14; ++j) psm[w * 33 + j] = red[j];
        } else if (lane == 16) {
            #pragma unroll
            for (int j = 0; j < 14; ++j) psm[w * 33 + 14 + j] = red[j];
        }
        __syncthreads();

        // ---- phase 2: warp w<14 sums 16 warp-partials for rows 2w, 2w+1 ----
        if (w < 14) {
            const int half = lane >> 4, li = lane & 15;
            float val = psm[li * 33 + 2 * w + half];
            #pragma unroll
            for (int m = 8; m >= 1; m >>= 1)
                val += __shfl_xor_sync(0xffffffffu, val, m);
            const float zA = __shfl_sync(0xffffffffu, val, 0);
            const float zB = __shfl_sync(0xffffffffu, val, 16);

            const float kA = tanhf(zA + bfA);
            const float kB = tanhf(zB + bfB);

            const float half_dt = 0.5f * dt;
            float vA, vB;
            if (u == 0)      { k1A = kA; k1B = kB; vA = hhA + half_dt * kA; vB = hhB + half_dt * kB; }
            else if (u == 1) { k2A = kA; k2B = kB; vA = hhA + half_dt * kA; vB = hhB + half_dt * kB; }
            else if (u == 2) { k3A = kA; k3B = kB; vA = hhA + dt * kA;      vB = hhB + dt * kB; }
            else {
                const float c = dt * (1.0f / 6.0f);
                hhA = hhA + c * (k1A + 2.0f * k2A + 2.0f * k3A + kA);
                hhB = hhB + c * (k1B + 2.0f * k2B + 2.0f * k3B + kB);
                vA = hhA; vB = hhB;
            }
            if (lane == 0) *(float2*)(&gV[p ^ 1][rA]) = make_float2(vA, vB);
        }

        tgt = bar_arrive();
        bar_wait(tgt);
        p ^= 1;
    }
    // hT is in gV[p]

    // ---- i2h: h_new = tanh(W_i2h @ [x; hT] + b_i2h)  (warps 0..13, rows 2w,2w+1) ----
    if (w < 14) {
        const float4* Wi4 = (const float4*)Wi;
        const float4* qA  = Wi4 + (size_t)cAi * CMB4;
        const float4* qB  = Wi4 + (size_t)cBi * CMB4;
        const float4* x4  = (const float4*)x;
        const float4* hT4 = (const float4*)gV[p];

        float4 A0 = make_float4(0.f,0.f,0.f,0.f);
        float4 A1 = A0;
        #pragma unroll
        for (int jj = 0; jj < 4; ++jj) {              // x part: 128 f4
            const int i = lane + 32 * jj;
            float4 b = __ldg(x4 + i);
            FMA4(A0, __ldg(qA + i), b);
            FMA4(A1, __ldg(qB + i), b);
        }
        #pragma unroll 4
        for (int k = 0; k < 32; ++k) {                // h part: 1024 f4
            const int i = lane + 32 * k;
            float4 b = __ldcg(hT4 + i);
            FMA4(A0, __ldg(qA + 128 + i), b);
            FMA4(A1, __ldg(qB + 128 + i), b);
        }
        const float zA = warp_sum((A0.x + A0.y) + (A0.z + A0.w));
        const float zB = warp_sum((A1.x + A1.y) + (A1.z + A1.w));

        if (lane == 0 && rA < NH) {
            const float hnA = tanhf(zA + __ldg(bi + cAi));
            const float hnB = tanhf(zB + __ldg(bi + cBi));
            *(float2*)(&gHn[rA])        = make_float2(hnA, hnB);
            *(float2*)(&out[NOUT + rA]) = make_float2(hnA, hnB);
        }
    }
    tgt = bar_arrive();
    bar_wait(tgt);

    // ---- h2o: out[0..127] (CTA cb<128, warp 0) ----
    if (blockIdx.x < NOUT && w == 0) {
        const int cb = blockIdx.x;
        const float4* pWo = (const float4*)Wo + (size_t)cb * NH4;
        const float4* hv  = (const float4*)gHn;
        float4 A = make_float4(0.f,0.f,0.f,0.f);
        #pragma unroll 4
        for (int k = 0; k < 32; ++k) {
            const int i = lane + 32 * k;
            FMA4(A, __ldg(pWo + i), __ldcg(hv + i));
        }
        const float z = warp_sum((A.x + A.y) + (A.z + A.w));
        if (lane == 0) out[cb] = z + __ldg(bo + cb);
    }
}

extern "C" void kernel_launch(void* const* d_in, const int* in_sizes, int n_in,
                              void* d_out, int out_size)
{
    const float* x   = (const float*)d_in[0];
    const float* h0  = (const float*)d_in[1];
    const float* t   = (const float*)d_in[2];
    const float* Wf  = (const float*)d_in[3];
    const float* bf  = (const float*)d_in[4];
    const float* Wi  = (const float*)d_in[5];
    const float* bi  = (const float*)d_in[6];
    const float* Wo  = (const float*)d_in[7];
    const float* bo  = (const float*)d_in[8];
    float* out = (float*)d_out;

    cudaFuncSetAttribute(ode_rnn_kernel,
                         cudaFuncAttributeMaxDynamicSharedMemorySize, SMEM_BYTES);
    ode_rnn_kernel<<<GRID, NTHREADS, SMEM_BYTES>>>(x, h0, t, Wf, bf, Wi, bi, Wo, bo, out);
}

// round 9
// speedup vs baseline: 1.1798x; 1.1798x over previous
#include <cuda_runtime.h>
#include <cstdint>

#define NH       4096
#define NH4      1024
#define NSTAGE   252                // 63 RK4 steps * 4 stages
#define NOUT     128
#define CMB4     1152

#define GRID     147
#define NW       14
#define NTHREADS 448
#define RPB      28                 // rows per CTA (2 per warp)
#define SW       13                 // rowA of warps 0..12 in SMEM

// smem: [13 Wf rows = 212992][v 16384][dt 256] = 229632 < 232448
#define OFF_VSM   212992
#define OFF_DT    229376
#define SMEM_BYTES 229632

__device__ __align__(16) float gV[2][4128];   // rows 0..4115 used (147*28)
__device__ __align__(16) float gHn[4128];
__device__ unsigned g_arrive;                 // single monotonic barrier counter

__device__ __forceinline__ unsigned bar_arrive() {
    __syncthreads();
    unsigned target = 0;
    if (threadIdx.x == 0) {
        unsigned old;
        asm volatile("atom.add.release.gpu.u32 %0, [%1], 1;"
                     : "=r"(old) : "l"(&g_arrive) : "memory");
        target = old - old % GRID + GRID;
    }
    return target;
}

__device__ __forceinline__ void bar_wait(unsigned target) {
    if (threadIdx.x == 0) {
        unsigned cur;
        do {
            asm volatile("ld.acquire.gpu.u32 %0, [%1];"
                         : "=r"(cur) : "l"(&g_arrive) : "memory");
        } while ((int)(cur - target) < 0);
    }
    __syncthreads();
}

__device__ __forceinline__ float warp_sum(float v) {
    #pragma unroll
    for (int o = 16; o; o >>= 1) v += __shfl_xor_sync(0xffffffffu, v, o);
    return v;
}

#define FMA4(A, Q, B) \
    { (A).x = fmaf((Q).x, (B).x, (A).x); (A).y = fmaf((Q).y, (B).y, (A).y); \
      (A).z = fmaf((Q).z, (B).z, (A).z); (A).w = fmaf((Q).w, (B).w, (A).w); }

__global__ void __launch_bounds__(NTHREADS, 1)
ode_rnn_kernel(const float* __restrict__ x,
               const float* __restrict__ h0,
               const float* __restrict__ t,
               const float* __restrict__ Wf,
               const float* __restrict__ bf,
               const float* __restrict__ Wi,
               const float* __restrict__ bi,
               const float* __restrict__ Wo,
               const float* __restrict__ bo,
               float* __restrict__ out)
{
    extern __shared__ char smem[];
    float4* wsm   = (float4*)smem;
    float4* vsm4  = (float4*)(smem + OFF_VSM);
    float*  dtbuf = (float*)(smem + OFF_DT);

    const int tid  = threadIdx.x;
    const int w    = tid >> 5;
    const int lane = tid & 31;
    const int half = lane >> 4;                 // 0: row A, 1: row B
    const int base = blockIdx.x * RPB;

    const int rA  = base + 2 * w;               // even
    const int cAi = min(rA,     NH - 1);
    const int cBi = min(rA + 1, NH - 1);
    const int myc = half ? cBi : cAi;

    const float4* Wf4 = (const float4*)Wf;
    const float4* pA  = Wf4 + (size_t)cAi * NH4;
    const float4* pB  = Wf4 + (size_t)cBi * NH4;
    const float4* waS = wsm + (size_t)w * NH4;
    const bool lastw  = (w == NW - 1);

    // ---- SMEM preload: rowA of warps 0..12 ----
    for (int idx = tid; idx < SW * NH4; idx += NTHREADS) {
        int slot   = idx >> 10;
        int within = idx & 1023;
        int gr     = min(base + 2 * slot, NH - 1);
        wsm[idx]   = __ldg(Wf4 + (size_t)gr * NH4 + within);
    }
    if (tid < NSTAGE / 4) dtbuf[tid] = __ldg(t + tid + 1) - __ldg(t + tid);

    // register cache: rowB chunks 0..11
    float4 cacheB[12];
    #pragma unroll
    for (int k = 0; k < 12; ++k) cacheB[k] = __ldg(pB + lane + 32 * k);

    // per-half RK4 state
    float hh  = __ldg(h0 + myc);
    const float bfv = __ldg(bf + myc);
    if (lane == 0 || lane == 16) gV[0][rA + half] = hh;

    float4 rb[6], ra[4];

    unsigned tgt = bar_arrive();
    // stage-0 window prefetch
    #pragma unroll
    for (int j = 0; j < 6; ++j) rb[j] = __ldg(pB + lane + 32 * (12 + j));
    if (lastw) {
        #pragma unroll
        for (int j = 0; j < 4; ++j) ra[j] = __ldg(pA + lane + 32 * j);
    }
    bar_wait(tgt);

    int p = 0;
    float k1 = 0.f, k2 = 0.f, k3 = 0.f;

    #pragma unroll 1
    for (int sg = 0; sg < NSTAGE; ++sg) {
        const float dt = dtbuf[sg >> 2];
        const int   u  = sg & 3;

        // ---- batched v loads (MLP=3), phase-1 store only ----
        const float4* src = (const float4*)gV[p];
        float4 t0 = __ldcg(src + tid);
        float4 t1 = __ldcg(src + tid + NTHREADS);
        float4 t2;
        const bool g3 = tid < (NH4 - 2 * NTHREADS);
        if (g3) t2 = __ldcg(src + tid + 2 * NTHREADS);
        vsm4[tid] = t0;
        __syncthreads();                          // vsm[0..447] ready

        float4 A0 = make_float4(0.f,0.f,0.f,0.f);
        float4 A1 = A0;

        if (!lastw) {
            #pragma unroll
            for (int k = 0; k < 12; ++k) {        // phase 1: reg-cached rowB
                const int i = lane + 32 * k;
                float4 b = vsm4[i];
                FMA4(A0, waS[i], b);
                FMA4(A1, cacheB[k], b);
            }
            #pragma unroll
            for (int k = 12; k < 14; ++k) {
                const int i = lane + 32 * k;
                float4 b = vsm4[i];
                float4 q = rb[k - 12];
                rb[k - 12] = __ldg(pB + i + 192); // chunk k+6
                FMA4(A0, waS[i], b);
                FMA4(A1, q, b);
            }
            // phase-2 v stores (loads returned under phase-1 compute)
            vsm4[tid + NTHREADS] = t1;
            if (g3) vsm4[tid + 2 * NTHREADS] = t2;
            __syncthreads();
            #pragma unroll
            for (int k = 14; k < 32; ++k) {
                const int i = lane + 32 * k;
                const int j = (k - 12) % 6;
                float4 b = vsm4[i];
                float4 q = rb[j];
                if (k < 26) rb[j] = __ldg(pB + i + 192);
                FMA4(A0, waS[i], b);
                FMA4(A1, q, b);
            }
        } else {
            #pragma unroll
            for (int k = 0; k < 12; ++k) {
                const int i = lane + 32 * k;
                float4 b  = vsm4[i];
                float4 qa = ra[k % 4];
                ra[k % 4] = __ldg(pA + i + 128);  // chunk k+4
                FMA4(A0, qa, b);
                FMA4(A1, cacheB[k], b);
            }
            #pragma unroll
            for (int k = 12; k < 14; ++k) {
                const int i = lane + 32 * k;
                float4 b  = vsm4[i];
                float4 qa = ra[k % 4];
                float4 qb = rb[k - 12];
                ra[k % 4]  = __ldg(pA + i + 128);
                rb[k - 12] = __ldg(pB + i + 192);
                FMA4(A0, qa, b);
                FMA4(A1, qb, b);
            }
            vsm4[tid + NTHREADS] = t1;
            if (g3) vsm4[tid + 2 * NTHREADS] = t2;
            __syncthreads();
            #pragma unroll
            for (int k = 14; k < 32; ++k) {
                const int i = lane + 32 * k;
                const int j = (k - 12) % 6;
                float4 b  = vsm4[i];
                float4 qa = ra[k % 4];
                float4 qb = rb[j];
                if (k < 28) ra[k % 4] = __ldg(pA + i + 128);
                if (k < 26) rb[j]     = __ldg(pB + i + 192);
                FMA4(A0, qa, b);
                FMA4(A1, qb, b);
            }
        }

        // ---- joint half-warp reduce: low half -> zA, high half -> zB ----
        const float sA = (A0.x + A0.y) + (A0.z + A0.w);
        const float sB = (A1.x + A1.y) + (A1.z + A1.w);
        const float lo = sA + __shfl_xor_sync(0xffffffffu, sA, 16);
        const float hi = sB + __shfl_xor_sync(0xffffffffu, sB, 16);
        float r = (lane < 16) ? lo : hi;
        #pragma unroll
        for (int m = 8; m; m >>= 1) r += __shfl_xor_sync(0xffffffffu, r, m);

        const float kk = tanhf(r + bfv);

        float vn;
        const float half_dt = 0.5f * dt;
        if (u == 0)      { k1 = kk; vn = hh + half_dt * kk; }
        else if (u == 1) { k2 = kk; vn = hh + half_dt * kk; }
        else if (u == 2) { k3 = kk; vn = hh + dt * kk; }
        else {
            hh = hh + (dt * (1.0f / 6.0f)) * (k1 + 2.0f * k2 + 2.0f * k3 + kk);
            vn = hh;
        }
        if (lane == 0 || lane == 16) gV[p ^ 1][rA + half] = vn;

        // arrive, window prefetch, wait
        tgt = bar_arrive();
        #pragma unroll
        for (int j = 0; j < 6; ++j) rb[j] = __ldg(pB + lane + 32 * (12 + j));
        if (lastw) {
            #pragma unroll
            for (int j = 0; j < 4; ++j) ra[j] = __ldg(pA + lane + 32 * j);
        }
        bar_wait(tgt);
        p ^= 1;
    }
    // hT in gV[p]

    // ---- i2h: h_new = tanh(W_i2h @ [x; hT] + b_i2h) ----
    {
        const float4* src = (const float4*)gV[p];
        for (int i = tid; i < NH4; i += NTHREADS) vsm4[i] = __ldcg(src + i);
        __syncthreads();

        const float4* Wi4 = (const float4*)Wi;
        const float4* qA  = Wi4 + (size_t)cAi * CMB4;
        const float4* qB  = Wi4 + (size_t)cBi * CMB4;
        const float4* x4  = (const float4*)x;

        float4 A0 = make_float4(0.f,0.f,0.f,0.f);
        float4 A1 = A0;
        #pragma unroll
        for (int jj = 0; jj < 4; ++jj) {
            const int i = lane + 32 * jj;
            float4 b = __ldg(x4 + i);
            FMA4(A0, __ldg(qA + i), b);
            FMA4(A1, __ldg(qB + i), b);
        }
        #pragma unroll 4
        for (int k = 0; k < 32; ++k) {
            const int i = lane + 32 * k;
            float4 b = vsm4[i];
            FMA4(A0, __ldg(qA + 128 + i), b);
            FMA4(A1, __ldg(qB + 128 + i), b);
        }
        const float zA = warp_sum((A0.x + A0.y) + (A0.z + A0.w));
        const float zB = warp_sum((A1.x + A1.y) + (A1.z + A1.w));

        if (lane == 0 && rA < NH) {
            const float hnA = tanhf(zA + __ldg(bi + cAi));
            const float hnB = tanhf(zB + __ldg(bi + cBi));
            *(float2*)(&gHn[rA])        = make_float2(hnA, hnB);
            *(float2*)(&out[NOUT + rA]) = make_float2(hnA, hnB);
        }
    }
    tgt = bar_arrive();
    bar_wait(tgt);

    // ---- h2o: out[0..127] (CTA cb<128, warp 0) ----
    if (blockIdx.x < NOUT && w == 0) {
        const int cb = blockIdx.x;
        const float4* pWo = (const float4*)Wo + (size_t)cb * NH4;
        const float4* hv  = (const float4*)gHn;
        float4 A = make_float4(0.f,0.f,0.f,0.f);
        #pragma unroll 4
        for (int k = 0; k < 32; ++k) {
            const int i = lane + 32 * k;
            FMA4(A, __ldg(pWo + i), __ldcg(hv + i));
        }
        const float z = warp_sum((A.x + A.y) + (A.z + A.w));
        if (lane == 0) out[cb] = z + __ldg(bo + cb);
    }
}

extern "C" void kernel_launch(void* const* d_in, const int* in_sizes, int n_in,
                              void* d_out, int out_size)
{
    const float* x   = (const float*)d_in[0];
    const float* h0  = (const float*)d_in[1];
    const float* t   = (const float*)d_in[2];
    const float* Wf  = (const float*)d_in[3];
    const float* bf  = (const float*)d_in[4];
    const float* Wi  = (const float*)d_in[5];
    const float* bi  = (const float*)d_in[6];
    const float* Wo  = (const float*)d_in[7];
    const float* bo  = (const float*)d_in[8];
    float* out = (float*)d_out;

    cudaFuncSetAttribute(ode_rnn_kernel,
                         cudaFuncAttributeMaxDynamicSharedMemorySize, SMEM_BYTES);
    ode_rnn_kernel<<<GRID, NTHREADS, SMEM_BYTES>>>(x, h0, t, Wf, bf, Wi, bi, Wo, bo, out);
}

// round 10
// speedup vs baseline: 1.2014x; 1.0182x over previous
#include <cuda_runtime.h>
#include <cstdint>

#define NH       4096
#define NH4      1024
#define NSTAGE   252                // 63 RK4 steps * 4 stages
#define NOUT     128
#define CMB4     1152

#define GRID     147
#define NW       15
#define NTHREADS 480
#define RPB      28                 // rows per CTA
#define SW       13                 // rowA of warps 0..12 in SMEM

// smem: [13 Wf rows = 212992][v 16384][dt 256] = 229632 < 232448
#define OFF_VSM   212992
#define OFF_DT    229376
#define SMEM_BYTES 229632

__device__ __align__(16) float gV[2][4128];   // rows 0..4115 used (147*28)
__device__ __align__(16) float gHn[4128];
__device__ unsigned g_arrive;                 // single monotonic barrier counter

__device__ __forceinline__ unsigned bar_arrive() {
    __syncthreads();
    unsigned target = 0;
    if (threadIdx.x == 0) {
        unsigned old;
        asm volatile("atom.add.release.gpu.u32 %0, [%1], 1;"
                     : "=r"(old) : "l"(&g_arrive) : "memory");
        target = old - old % GRID + GRID;
    }
    return target;
}

__device__ __forceinline__ void bar_wait(unsigned target) {
    if (threadIdx.x == 0) {
        unsigned cur;
        do {
            asm volatile("ld.acquire.gpu.u32 %0, [%1];"
                         : "=r"(cur) : "l"(&g_arrive) : "memory");
        } while ((int)(cur - target) < 0);
    }
    __syncthreads();
}

__device__ __forceinline__ float warp_sum(float v) {
    #pragma unroll
    for (int o = 16; o; o >>= 1) v += __shfl_xor_sync(0xffffffffu, v, o);
    return v;
}

#define FMA4(A, Q, B) \
    { (A).x = fmaf((Q).x, (B).x, (A).x); (A).y = fmaf((Q).y, (B).y, (A).y); \
      (A).z = fmaf((Q).z, (B).z, (A).z); (A).w = fmaf((Q).w, (B).w, (A).w); }

__global__ void __launch_bounds__(NTHREADS, 1)
ode_rnn_kernel(const float* __restrict__ x,
               const float* __restrict__ h0,
               const float* __restrict__ t,
               const float* __restrict__ Wf,
               const float* __restrict__ bf,
               const float* __restrict__ Wi,
               const float* __restrict__ bi,
               const float* __restrict__ Wo,
               const float* __restrict__ bo,
               float* __restrict__ out)
{
    extern __shared__ char smem[];
    float4* wsm   = (float4*)smem;
    float4* vsm4  = (float4*)(smem + OFF_VSM);
    float*  dtbuf = (float*)(smem + OFF_DT);

    const int tid  = threadIdx.x;
    const int w    = tid >> 5;
    const int lane = tid & 31;
    const int half = lane >> 4;
    const int base = blockIdx.x * RPB;

    const bool paired = (w < 13);               // w13,w14: single L2 row each
    const int rA   = base + 2 * w;              // paired rows rA, rA+1 (w13: i2h rows 26,27)
    const int rowT = base + 26 + (w - 13);      // tail-owned row (w13: +26, w14: +27)

    const int cAi = min(rA,     NH - 1);
    const int cBi = min(rA + 1, NH - 1);

    const float4* Wf4 = (const float4*)Wf;
    // L2-streamed row for this warp: rowB (paired) or rowT (tail)
    const int cS = paired ? cBi : min(rowT, NH - 1);
    const float4* pB  = Wf4 + (size_t)cS * NH4;
    const float4* waS = wsm + (size_t)min(w, 12) * NH4;

    // ---- SMEM preload: rowA of warps 0..12 ----
    for (int idx = tid; idx < SW * NH4; idx += NTHREADS) {
        int slot   = idx >> 10;
        int within = idx & 1023;
        int gr     = min(base + 2 * slot, NH - 1);
        wsm[idx]   = __ldg(Wf4 + (size_t)gr * NH4 + within);
    }
    if (tid < NSTAGE / 4) dtbuf[tid] = __ldg(t + tid + 1) - __ldg(t + tid);

    // register cache for the streamed row: chunks 0..13
    float4 cacheB[14];
    #pragma unroll
    for (int k = 0; k < 14; ++k) cacheB[k] = __ldg(pB + lane + 32 * k);

    // RK4 state: paired -> per half-lane (lane<16 rowA, else rowB); tail -> whole warp one row
    const int myc = paired ? (half ? cBi : cAi) : cS;
    float hh  = __ldg(h0 + myc);
    const float bfv = __ldg(bf + myc);
    if (paired) {
        if (lane == 0 || lane == 16) gV[0][rA + half] = hh;
    } else {
        if (lane == 0) gV[0][rowT] = hh;
    }

    float4 rb[6];
    unsigned tgt = bar_arrive();
    #pragma unroll
    for (int j = 0; j < 6; ++j) rb[j] = __ldg(pB + lane + 32 * (14 + j));
    bar_wait(tgt);

    int p = 0;
    float k1 = 0.f, k2 = 0.f, k3 = 0.f;

    #pragma unroll 1
    for (int sg = 0; sg < NSTAGE; ++sg) {
        const float dt = dtbuf[sg >> 2];
        const int   u  = sg & 3;

        // ---- batched v loads (MLP=3), phase-1 store ----
        const float4* src = (const float4*)gV[p];
        float4 t0 = __ldcg(src + tid);
        float4 t1 = __ldcg(src + tid + NTHREADS);
        float4 t2;
        const bool g3 = tid < (NH4 - 2 * NTHREADS);   // tid < 64
        if (g3) t2 = __ldcg(src + tid + 2 * NTHREADS);
        vsm4[tid] = t0;
        __syncthreads();                               // vsm[0..479] ready (chunks 0..14)

        float4 A0 = make_float4(0.f,0.f,0.f,0.f);
        float4 A1 = A0;

        // ---- phase 1: chunks 0..14 ----
        if (paired) {
            #pragma unroll
            for (int k = 0; k < 14; ++k) {
                const int i = lane + 32 * k;
                float4 b = vsm4[i];
                FMA4(A0, waS[i], b);
                FMA4(A1, cacheB[k], b);
            }
            {
                const int i = lane + 32 * 14;
                float4 b = vsm4[i];
                float4 q = rb[0];
                rb[0] = __ldg(pB + i + 192);           // chunk 20
                FMA4(A0, waS[i], b);
                FMA4(A1, q, b);
            }
        } else {
            #pragma unroll
            for (int k = 0; k < 14; ++k) {
                const int i = lane + 32 * k;
                FMA4(A1, cacheB[k], vsm4[i]);
            }
            {
                const int i = lane + 32 * 14;
                float4 q = rb[0];
                rb[0] = __ldg(pB + i + 192);
                FMA4(A1, q, vsm4[i]);
            }
        }

        // ---- phase-2 v stores (loads returned under phase-1 compute) ----
        vsm4[tid + NTHREADS] = t1;
        if (g3) vsm4[tid + 2 * NTHREADS] = t2;
        __syncthreads();

        // ---- phase 2: chunks 15..31 ----
        if (paired) {
            #pragma unroll
            for (int k = 15; k < 32; ++k) {
                const int i = lane + 32 * k;
                const int j = (k - 14) % 6;
                float4 b = vsm4[i];
                float4 q = rb[j];
                if (k < 26) rb[j] = __ldg(pB + i + 192);
                FMA4(A0, waS[i], b);
                FMA4(A1, q, b);
            }
        } else {
            #pragma unroll
            for (int k = 15; k < 32; ++k) {
                const int i = lane + 32 * k;
                const int j = (k - 14) % 6;
                float4 q = rb[j];
                if (k < 26) rb[j] = __ldg(pB + i + 192);
                FMA4(A1, q, vsm4[i]);
            }
        }

        // ---- reduce + RK4 + publish ----
        float kk;
        if (paired) {
            const float sA = (A0.x + A0.y) + (A0.z + A0.w);
            const float sB = (A1.x + A1.y) + (A1.z + A1.w);
            const float lo = sA + __shfl_xor_sync(0xffffffffu, sA, 16);
            const float hi = sB + __shfl_xor_sync(0xffffffffu, sB, 16);
            float r = (lane < 16) ? lo : hi;
            #pragma unroll
            for (int m = 8; m; m >>= 1) r += __shfl_xor_sync(0xffffffffu, r, m);
            kk = tanhf(r + bfv);
        } else {
            const float z = warp_sum((A1.x + A1.y) + (A1.z + A1.w));
            kk = tanhf(z + bfv);
        }

        float vn;
        const float half_dt = 0.5f * dt;
        if (u == 0)      { k1 = kk; vn = hh + half_dt * kk; }
        else if (u == 1) { k2 = kk; vn = hh + half_dt * kk; }
        else if (u == 2) { k3 = kk; vn = hh + dt * kk; }
        else {
            hh = hh + (dt * (1.0f / 6.0f)) * (k1 + 2.0f * k2 + 2.0f * k3 + kk);
            vn = hh;
        }
        if (paired) {
            if (lane == 0 || lane == 16) gV[p ^ 1][rA + half] = vn;
        } else {
            if (lane == 0) gV[p ^ 1][rowT] = vn;
        }

        // arrive, window-prefetch next stage's ring, wait
        tgt = bar_arrive();
        #pragma unroll
        for (int j = 0; j < 6; ++j) rb[j] = __ldg(pB + lane + 32 * (14 + j));
        bar_wait(tgt);
        p ^= 1;
    }
    // hT in gV[p]

    // ---- i2h: h_new = tanh(W_i2h @ [x; hT] + b_i2h)  (warps 0..13: rows 2w, 2w+1) ----
    {
        const float4* src = (const float4*)gV[p];
        for (int i = tid; i < NH4; i += NTHREADS) vsm4[i] = __ldcg(src + i);
        __syncthreads();

        if (w < 14) {
            const float4* Wi4 = (const float4*)Wi;
            const float4* qA  = Wi4 + (size_t)cAi * CMB4;
            const float4* qB  = Wi4 + (size_t)cBi * CMB4;
            const float4* x4  = (const float4*)x;

            float4 A0 = make_float4(0.f,0.f,0.f,0.f);
            float4 A1 = A0;
            #pragma unroll
            for (int jj = 0; jj < 4; ++jj) {
                const int i = lane + 32 * jj;
                float4 b = __ldg(x4 + i);
                FMA4(A0, __ldg(qA + i), b);
                FMA4(A1, __ldg(qB + i), b);
            }
            #pragma unroll 4
            for (int k = 0; k < 32; ++k) {
                const int i = lane + 32 * k;
                float4 b = vsm4[i];
                FMA4(A0, __ldg(qA + 128 + i), b);
                FMA4(A1, __ldg(qB + 128 + i), b);
            }
            const float zA = warp_sum((A0.x + A0.y) + (A0.z + A0.w));
            const float zB = warp_sum((A1.x + A1.y) + (A1.z + A1.w));

            if (lane == 0 && rA < NH) {
                const float hnA = tanhf(zA + __ldg(bi + cAi));
                const float hnB = tanhf(zB + __ldg(bi + cBi));
                *(float2*)(&gHn[rA])        = make_float2(hnA, hnB);
                *(float2*)(&out[NOUT + rA]) = make_float2(hnA, hnB);
            }
        }
    }
    tgt = bar_arrive();
    bar_wait(tgt);

    // ---- h2o: out[0..127] (CTA cb<128, warp 0) ----
    if (blockIdx.x < NOUT && w == 0) {
        const int cb = blockIdx.x;
        const float4* pWo = (const float4*)Wo + (size_t)cb * NH4;
        const float4* hv  = (const float4*)gHn;
        float4 A = make_float4(0.f,0.f,0.f,0.f);
        #pragma unroll 4
        for (int k = 0; k < 32; ++k) {
            const int i = lane + 32 * k;
            FMA4(A, __ldg(pWo + i), __ldcg(hv + i));
        }
        const float z = warp_sum((A.x + A.y) + (A.z + A.w));
        if (lane == 0) out[cb] = z + __ldg(bo + cb);
    }
}

extern "C" void kernel_launch(void* const* d_in, const int* in_sizes, int n_in,
                              void* d_out, int out_size)
{
    const float* x   = (const float*)d_in[0];
    const float* h0  = (const float*)d_in[1];
    const float* t   = (const float*)d_in[2];
    const float* Wf  = (const float*)d_in[3];
    const float* bf  = (const float*)d_in[4];
    const float* Wi  = (const float*)d_in[5];
    const float* bi  = (const float*)d_in[6];
    const float* Wo  = (const float*)d_in[7];
    const float* bo  = (const float*)d_in[8];
    float* out = (float*)d_out;

    cudaFuncSetAttribute(ode_rnn_kernel,
                         cudaFuncAttributeMaxDynamicSharedMemorySize, SMEM_BYTES);
    ode_rnn_kernel<<<GRID, NTHREADS, SMEM_BYTES>>>(x, h0, t, Wf, bf, Wi, bi, Wo, bo, out);
}